// round 11
// baseline (speedup 1.0000x reference)
#include <cuda_runtime.h>
#include <cstdint>

#define Tn 4096   // B*S tokens
#define Dn 1024
#define En 8
#define Fn 4096
#define Bb 8
#define Sn 512

// ---------------- scratch (device globals; no allocations) ----------------
__device__ float g_lin[Tn * Dn];
__device__ float g_accb[Tn * Dn];              // x + moe accumulation
__device__ float g_h[2 * Tn * Fn];
__device__ float g_w1t[(size_t)En * Fn * Dn];  // w1 transposed: [e][n=F][k=D]
__device__ float g_w2t[(size_t)En * Dn * Fn];  // w2 transposed: [e][n=D][k=F]
__device__ float g_wc[Dn * En];                // folded gate: x@Wc = gate logits
__device__ float g_bc[En];
__device__ int   g_tok[2 * Tn];
__device__ float g_tw[2 * Tn];
__device__ int   g_cnt[En], g_off[En], g_fill[En];
__device__ int   g_gi[Tn * 2];
__device__ float g_gw[Tn * 2];
__device__ float g_sent[Bb * Dn];

// ---------------- helpers ----------------
__device__ __forceinline__ uint32_t s2u(const void* p) {
    uint32_t a;
    asm("{ .reg .u64 t; cvta.to.shared.u64 t, %1; cvt.u32.u64 %0, t; }" : "=r"(a) : "l"(p));
    return a;
}
__device__ __forceinline__ void mma8(float* c, const uint32_t* a,
                                     uint32_t b0, uint32_t b1) {
    asm volatile(
        "mma.sync.aligned.m16n8k8.row.col.f32.tf32.tf32.f32 "
        "{%0,%1,%2,%3},{%4,%5,%6,%7},{%8,%9},{%0,%1,%2,%3};"
        : "+f"(c[0]), "+f"(c[1]), "+f"(c[2]), "+f"(c[3])
        : "r"(a[0]), "r"(a[1]), "r"(a[2]), "r"(a[3]), "r"(b0), "r"(b1));
}
__device__ __forceinline__ void ldmx4(uint32_t* r, uint32_t a) {
    asm volatile("ldmatrix.sync.aligned.m8n8.x4.shared.b16 {%0,%1,%2,%3},[%4];"
                 : "=r"(r[0]), "=r"(r[1]), "=r"(r[2]), "=r"(r[3]) : "r"(a));
}
#define CPA(dst, src) \
    asm volatile("cp.async.cg.shared.global [%0], [%1], 16;" :: "r"(dst), "l"(src) : "memory")
#define CPCOMMIT() asm volatile("cp.async.commit_group;" ::: "memory")
#define CPWAIT0()  asm volatile("cp.async.wait_group 0;" ::: "memory")
#define CPWAIT1()  asm volatile("cp.async.wait_group 1;" ::: "memory")

// ---------------- weight transpose: [e][R][C] -> [e][C][R] ----------------
__global__ void __launch_bounds__(256) k_tr(const float* __restrict__ src,
                                            float* __restrict__ dst, int R, int C) {
    __shared__ float t[32][33];
    int e = blockIdx.z;
    const float* s = src + (size_t)e * R * C;
    float* d = dst + (size_t)e * R * C;
    int c0 = blockIdx.x * 32, r0 = blockIdx.y * 32;
    int tx = threadIdx.x & 31, ty = threadIdx.x >> 5;
#pragma unroll
    for (int i = 0; i < 4; i++)
        t[ty + 8 * i][tx] = s[(size_t)(r0 + ty + 8 * i) * C + c0 + tx];
    __syncthreads();
#pragma unroll
    for (int i = 0; i < 4; i++)
        d[(size_t)(c0 + ty + 8 * i) * R + r0 + tx] = t[tx][ty + 8 * i];
}

// ---------------- Wc = W^T @ Wg (exact fp32), bc = b @ Wg ----------------
__global__ void __launch_bounds__(256) k_wc(const float* __restrict__ W,
                                            const float* __restrict__ Wg,
                                            const float* __restrict__ b) {
    __shared__ float swg[Dn * En];
    for (int i = threadIdx.x; i < Dn * En; i += 256) swg[i] = Wg[i];
    __syncthreads();
    int d = blockIdx.x * 256 + threadIdx.x;
    float acc[En] = {};
    for (int ep = 0; ep < Dn; ep++) {
        float wv = W[(size_t)ep * Dn + d];
        const float* wg = &swg[ep * En];
#pragma unroll
        for (int e = 0; e < En; e++) acc[e] += wv * wg[e];
    }
#pragma unroll
    for (int e = 0; e < En; e++) g_wc[d * En + e] = acc[e];
    if (blockIdx.x == 0 && threadIdx.x < En) {
        float s = 0.f;
        for (int ep = 0; ep < Dn; ep++) s += b[ep] * swg[ep * En + threadIdx.x];
        g_bc[threadIdx.x] = s;
    }
}

// ---------------- init: acc = x, zero counters ----------------
__global__ void k_init(const float* __restrict__ x) {
    if (blockIdx.x == 0 && threadIdx.x < En) g_cnt[threadIdx.x] = 0;
    int st = gridDim.x * blockDim.x;
    for (int i = blockIdx.x * blockDim.x + threadIdx.x; i < Tn * Dn; i += st)
        g_accb[i] = x[i];
}

// ---------------- gate from x via folded Wc (exact fp32 top-2) -------------
__global__ void k_gate2(const float* __restrict__ x) {
    int warp = (blockIdx.x * blockDim.x + threadIdx.x) >> 5;
    int lane = threadIdx.x & 31;
    if (warp >= Tn) return;
    const float* xr = &x[(size_t)warp * Dn];
    float p[En] = {};
    for (int i = lane; i < Dn; i += 32) {
        float v = xr[i];
        const float* w = &g_wc[i * En];
#pragma unroll
        for (int e = 0; e < En; e++) p[e] += v * w[e];
    }
#pragma unroll
    for (int o = 16; o; o >>= 1)
#pragma unroll
        for (int e = 0; e < En; e++) p[e] += __shfl_xor_sync(0xffffffffu, p[e], o);
    if (lane == 0) {
#pragma unroll
        for (int e = 0; e < En; e++) p[e] += g_bc[e];
        int i1 = 0;
        for (int e = 1; e < En; e++) if (p[e] > p[i1]) i1 = e;
        int i2 = -1;
        for (int e = 0; e < En; e++)
            if (e != i1 && (i2 < 0 || p[e] > p[i2])) i2 = e;
        float w1 = 1.f / (1.f + expf(p[i2] - p[i1]));
        g_gi[warp * 2] = i1; g_gi[warp * 2 + 1] = i2;
        g_gw[warp * 2] = w1; g_gw[warp * 2 + 1] = 1.f - w1;
        atomicAdd(&g_cnt[i1], 1);
        atomicAdd(&g_cnt[i2], 1);
    }
}

__global__ void k_off() {
    int a = 0;
    for (int e = 0; e < En; e++) { g_off[e] = a; a += g_cnt[e]; g_fill[e] = 0; }
}

__global__ void k_scatter() {
    int t = blockIdx.x * blockDim.x + threadIdx.x;
    if (t >= Tn) return;
#pragma unroll
    for (int k = 0; k < 2; k++) {
        int e = g_gi[t * 2 + k];
        int slot = g_off[e] + atomicAdd(&g_fill[e], 1);
        g_tok[slot] = t;
        g_tw[slot]  = g_gw[t * 2 + k];
    }
}

// ==== 3-stage cp.async tf32 GEMM, ldmatrix feeds: 128x128 tile, Kc=32 ======
// All B operands are [n][k] (k-contiguous): pure cp.async staging, 1 barrier/chunk.
// MODE 0: g_lin = x @ W^T + b              (KD=Dn)
// MODE 1: g_h = relu(lin[g_tok]@w1t[e]+b1) (KD=Dn)
// MODE 2: g_accb += gw*(g_h@w2t[e]+b2)     (KD=Fn)
template<int KD, int MODE>
__global__ void __launch_bounds__(256) pipe_ffn(const float* __restrict__ Asrc,
                                                const float* __restrict__ Bw,
                                                const float* __restrict__ bias)
{
    extern __shared__ float sm[];
    constexpr int STR = 36;                       // 144B rows: ldmatrix conflict-free
    constexpr uint32_t STGB = 128 * STR * 4;      // 18432 B per stage per operand
    float* Asm = sm;                              // [3][128][36]
    float* Bsm = sm + 3 * 128 * STR;              // [3][128][36]

    int e = (MODE == 0) ? 0 : blockIdx.z;
    int cnt = (MODE == 0) ? Tn : g_cnt[e];
    int row0 = blockIdx.x * 128;
    if (MODE != 0 && row0 >= cnt) return;
    int off = (MODE == 0) ? 0 : g_off[e];
    int col0 = blockIdx.y * 128;
    int tid = threadIdx.x, warp = tid >> 5, lane = tid & 31;
    int warpM = warp >> 1, warpN = warp & 1;
    int grp = lane >> 2, tig = lane & 3;
    int mBase = warpM * 32, nBase = warpN * 64;

    uint32_t Au = s2u(Asm), Bu = s2u(Bsm);

    // staging: row ar (2 threads/row, 16 floats each), both operands
    int ar = tid >> 1, ac = (tid & 1) * 16;
    const float* asrc;
    if (MODE == 0) {
        asrc = Asrc + (size_t)(row0 + ar) * KD;
    } else if (MODE == 1) {
        int r = row0 + ar;
        int tok = (r < cnt) ? g_tok[off + r] : g_tok[off];
        asrc = g_lin + (size_t)tok * KD;
    } else {
        int s = off + row0 + ar; if (s >= 2 * Tn) s = 0;
        asrc = g_h + (size_t)s * KD;
    }
    // B: [n][k] with per-expert block of Dn*Fn elements (FIX vs R10: expert offset)
    const float* bsrc = Bw + (MODE != 0 ? (size_t)e * Dn * Fn : 0)
                           + (size_t)(col0 + ar) * KD;
    asrc += ac; bsrc += ac;
    uint32_t aDst0 = Au + ((uint32_t)ar * STR + ac) * 4;
    uint32_t bDst0 = Bu + ((uint32_t)ar * STR + ac) * 4;

    auto stage = [&](int it, int buf) {
        uint32_t so = (uint32_t)buf * STGB;
        const float* as = asrc + it * 32;
        const float* bs = bsrc + it * 32;
#pragma unroll
        for (int j = 0; j < 4; j++) CPA(aDst0 + so + j * 16, as + j * 4);
#pragma unroll
        for (int j = 0; j < 4; j++) CPA(bDst0 + so + j * 16, bs + j * 4);
        CPCOMMIT();
    };

    stage(0, 0);
    stage(1, 1);

    // ldmatrix lane base addresses (fragment layout proven in R9)
    uint32_t aB0 = Au + (uint32_t)((mBase + (lane & 7) + 8 * ((lane >> 3) & 1)) * STR
                                   + 4 * (lane >> 4)) * 4;
    uint32_t aB1 = aB0 + 16 * STR * 4;
    uint32_t bB[4];
#pragma unroll
    for (int p = 0; p < 4; p++)
        bB[p] = Bu + (uint32_t)((nBase + p * 16 + (lane & 7) + 8 * (lane >> 4)) * STR
                                + 4 * ((lane >> 3) & 1)) * 4;

    float cc[2][8][4] = {};
    constexpr int NK = KD / 32;
    int buf = 0, nbuf = 2;     // buf = it%3; nbuf = (it+2)%3
    for (int it = 0; it < NK; ++it) {
        if (it + 2 < NK) { CPWAIT1(); } else { CPWAIT0(); }
        __syncthreads();       // buf ready; buffer (it-1)%3 freed by all warps
        if (it + 2 < NK) stage(it + 2, nbuf);
        uint32_t so = (uint32_t)buf * STGB;
#pragma unroll
        for (int ks = 0; ks < 32; ks += 8) {
            uint32_t af0[4], af1[4], bf[4][4];
            ldmx4(af0, aB0 + so + ks * 4);
            ldmx4(af1, aB1 + so + ks * 4);
#pragma unroll
            for (int p = 0; p < 4; p++) ldmx4(bf[p], bB[p] + so + ks * 4);
#pragma unroll
            for (int p = 0; p < 4; p++) {
                mma8(cc[0][2 * p],     af0, bf[p][0], bf[p][1]);
                mma8(cc[0][2 * p + 1], af0, bf[p][2], bf[p][3]);
                mma8(cc[1][2 * p],     af1, bf[p][0], bf[p][1]);
                mma8(cc[1][2 * p + 1], af1, bf[p][2], bf[p][3]);
            }
        }
        buf = buf == 2 ? 0 : buf + 1;
        nbuf = nbuf == 2 ? 0 : nbuf + 1;
    }

    // ---- epilogue ----
#pragma unroll
    for (int mt = 0; mt < 2; mt++)
#pragma unroll
    for (int half = 0; half < 2; half++) {
        int r = row0 + mBase + mt * 16 + grp + half * 8;
        if (MODE != 0 && r >= cnt) continue;
        int slot = off + r;
        if (MODE == 0) {
            float* o = g_lin + (size_t)r * Dn + col0;
#pragma unroll
            for (int nt = 0; nt < 8; nt++) {
                int c = nBase + nt * 8 + 2 * tig;
                float2 v;
                v.x = cc[mt][nt][half * 2 + 0] + bias[col0 + c];
                v.y = cc[mt][nt][half * 2 + 1] + bias[col0 + c + 1];
                *(float2*)(o + c) = v;
            }
        } else if (MODE == 1) {
            float* o = g_h + (size_t)slot * Fn + col0;
#pragma unroll
            for (int nt = 0; nt < 8; nt++) {
                int c = nBase + nt * 8 + 2 * tig;
                float2 v;
                v.x = fmaxf(cc[mt][nt][half * 2 + 0] + bias[e * Fn + col0 + c], 0.f);
                v.y = fmaxf(cc[mt][nt][half * 2 + 1] + bias[e * Fn + col0 + c + 1], 0.f);
                *(float2*)(o + c) = v;
            }
        } else {
            int tok = g_tok[slot];
            float gw = g_tw[slot];
            float* o = g_accb + (size_t)tok * Dn + col0;
#pragma unroll
            for (int nt = 0; nt < 8; nt++) {
                int c = nBase + nt * 8 + 2 * tig;
                atomicAdd(&o[c],     gw * (cc[mt][nt][half * 2 + 0] + bias[e * Dn + col0 + c]));
                atomicAdd(&o[c + 1], gw * (cc[mt][nt][half * 2 + 1] + bias[e * Dn + col0 + c + 1]));
            }
        }
    }
}

// ---------------- mean pool + loss ----------------
__global__ void k_sent(float* out) {
    int i = blockIdx.x * blockDim.x + threadIdx.x;
    if (i == 0) out[0] = 0.f;
    if (i >= Bb * Dn) return;
    int b = i >> 10, d = i & 1023;
    const float* p = &g_accb[(size_t)(b * Sn) * Dn + d];
    float s = 0.f;
    for (int si = 0; si < Sn; si++) s += p[si * Dn];
    g_sent[i] = s * (1.f / Sn);
}

__global__ void k_loss(const int* __restrict__ y, float* out) {
    int b = blockIdx.x, tid = threadIdx.x;
    __shared__ float red[256];
    const float* s = &g_sent[b * Dn];
    float m = -1e30f;
    for (int i = tid; i < Dn; i += 256) m = fmaxf(m, s[i]);
    red[tid] = m; __syncthreads();
    for (int o = 128; o; o >>= 1) {
        if (tid < o) red[tid] = fmaxf(red[tid], red[tid + o]);
        __syncthreads();
    }
    float mx = red[0]; __syncthreads();
    float sum = 0.f;
    for (int i = tid; i < Dn; i += 256) sum += expf(s[i] - mx);
    red[tid] = sum; __syncthreads();
    for (int o = 128; o; o >>= 1) {
        if (tid < o) red[tid] += red[tid + o];
        __syncthreads();
    }
    if (tid == 0)
        atomicAdd(out, -(s[y[b]] - (mx + logf(red[0]))) * (1.f / Bb));
}

// ---------------- launch ----------------
extern "C" void kernel_launch(void* const* d_in, const int* in_sizes, int n_in,
                              void* d_out, int out_size) {
    const float* x  = (const float*)d_in[0];
    const int*   y  = (const int*)d_in[1];
    const float* W  = (const float*)d_in[2];
    const float* bb = (const float*)d_in[3];
    const float* Wg = (const float*)d_in[4];
    const float* w1 = (const float*)d_in[5];
    const float* b1 = (const float*)d_in[6];
    const float* w2 = (const float*)d_in[7];
    const float* b2 = (const float*)d_in[8];
    float* out = (float*)d_out;

    constexpr int SMEMB = 6 * 128 * 36 * 4;  // 110592 B (3 stages x A+B)
    static int done = 0;
    if (!done) {
        cudaFuncSetAttribute((const void*)pipe_ffn<Dn, 0>,
                             cudaFuncAttributeMaxDynamicSharedMemorySize, SMEMB);
        cudaFuncSetAttribute((const void*)pipe_ffn<Dn, 1>,
                             cudaFuncAttributeMaxDynamicSharedMemorySize, SMEMB);
        cudaFuncSetAttribute((const void*)pipe_ffn<Fn, 2>,
                             cudaFuncAttributeMaxDynamicSharedMemorySize, SMEMB);
        done = 1;
    }

    float* w1t; cudaGetSymbolAddress((void**)&w1t, g_w1t);
    float* w2t; cudaGetSymbolAddress((void**)&w2t, g_w2t);
    k_tr<<<dim3(Fn / 32, Dn / 32, En), 256>>>(w1, w1t, Dn, Fn);
    k_tr<<<dim3(Dn / 32, Fn / 32, En), 256>>>(w2, w2t, Fn, Dn);

    k_wc<<<Dn / 256, 256>>>(W, Wg, bb);
    k_init<<<256, 256>>>(x);
    k_gate2<<<(Tn * 32) / 256, 256>>>(x);
    pipe_ffn<Dn, 0><<<dim3(Tn / 128, Dn / 128, 1), 256, SMEMB>>>(x, W, bb);
    k_off<<<1, 1>>>();
    k_scatter<<<Tn / 256, 256>>>();
    pipe_ffn<Dn, 1><<<dim3(Tn / 128, Fn / 128, En), 256, SMEMB>>>(nullptr, w1t, b1);
    pipe_ffn<Fn, 2><<<dim3(Tn / 128, Dn / 128, En), 256, SMEMB>>>(nullptr, w2t, b2);
    k_sent<<<(Bb * Dn + 255) / 256, 256>>>(out);
    k_loss<<<Bb, 256>>>(y, out);
}

// round 12
// speedup vs baseline: 1.1388x; 1.1388x over previous
#include <cuda_runtime.h>
#include <cstdint>

#define Tn 4096   // B*S tokens
#define Dn 1024
#define En 8
#define Fn 4096
#define Bb 8
#define Sn 512

// ---------------- scratch (device globals; no allocations) ----------------
__device__ float g_lin[Tn * Dn];
__device__ float g_h[2 * Tn * Fn];
__device__ float g_moe[2 * Tn * Dn];   // per-topk-slot expert outputs (no atomics)
__device__ float g_wc[Dn * En];        // folded gate: x@Wc = gate logits
__device__ float g_bc[En];
__device__ int   g_tok[2 * Tn];
__device__ int   g_tk[2 * Tn];         // which top-k slot (0/1) this routing entry is
__device__ float g_tw[2 * Tn];
__device__ int   g_cnt[En], g_off[En], g_fill[En];
__device__ int   g_gi[Tn * 2];
__device__ float g_gw[Tn * 2];
__device__ float g_sent[Bb * Dn];

// ---------------- helpers ----------------
__device__ __forceinline__ uint32_t s2u(const void* p) {
    uint32_t a;
    asm("{ .reg .u64 t; cvta.to.shared.u64 t, %1; cvt.u32.u64 %0, t; }" : "=r"(a) : "l"(p));
    return a;
}
__device__ __forceinline__ void mma8(float* c, const uint32_t* a,
                                     uint32_t b0, uint32_t b1) {
    asm volatile(
        "mma.sync.aligned.m16n8k8.row.col.f32.tf32.tf32.f32 "
        "{%0,%1,%2,%3},{%4,%5,%6,%7},{%8,%9},{%0,%1,%2,%3};"
        : "+f"(c[0]), "+f"(c[1]), "+f"(c[2]), "+f"(c[3])
        : "r"(a[0]), "r"(a[1]), "r"(a[2]), "r"(a[3]), "r"(b0), "r"(b1));
}
__device__ __forceinline__ void ldmx4(uint32_t* r, uint32_t a) {
    asm volatile("ldmatrix.sync.aligned.m8n8.x4.shared.b16 {%0,%1,%2,%3},[%4];"
                 : "=r"(r[0]), "=r"(r[1]), "=r"(r[2]), "=r"(r[3]) : "r"(a));
}
#define CPA(dst, src) \
    asm volatile("cp.async.cg.shared.global [%0], [%1], 16;" :: "r"(dst), "l"(src) : "memory")
#define CPCOMMIT() asm volatile("cp.async.commit_group;" ::: "memory")
#define CPWAIT0()  asm volatile("cp.async.wait_group 0;" ::: "memory")
#define CPWAIT1()  asm volatile("cp.async.wait_group 1;" ::: "memory")

// ---------------- Wc = W^T @ Wg (exact fp32), bc = b @ Wg ----------------
__global__ void __launch_bounds__(256) k_wc(const float* __restrict__ W,
                                            const float* __restrict__ Wg,
                                            const float* __restrict__ b) {
    __shared__ float swg[Dn * En];
    for (int i = threadIdx.x; i < Dn * En; i += 256) swg[i] = Wg[i];
    __syncthreads();
    int d = blockIdx.x * 256 + threadIdx.x;
    float acc[En] = {};
    for (int ep = 0; ep < Dn; ep++) {
        float wv = W[(size_t)ep * Dn + d];
        const float* wg = &swg[ep * En];
#pragma unroll
        for (int e = 0; e < En; e++) acc[e] += wv * wg[e];
    }
#pragma unroll
    for (int e = 0; e < En; e++) g_wc[d * En + e] = acc[e];
    if (blockIdx.x == 0 && threadIdx.x < En) {
        float s = 0.f;
        for (int ep = 0; ep < Dn; ep++) s += b[ep] * swg[ep * En + threadIdx.x];
        g_bc[threadIdx.x] = s;
    }
}

// ---------------- init: zero expert counters only ----------------
__global__ void k_init() {
    if (threadIdx.x < En) g_cnt[threadIdx.x] = 0;
}

// ---------------- gate from x via folded Wc (exact fp32 top-2) -------------
__global__ void k_gate2(const float* __restrict__ x) {
    int warp = (blockIdx.x * blockDim.x + threadIdx.x) >> 5;
    int lane = threadIdx.x & 31;
    if (warp >= Tn) return;
    const float* xr = &x[(size_t)warp * Dn];
    float p[En] = {};
    for (int i = lane; i < Dn; i += 32) {
        float v = xr[i];
        const float* w = &g_wc[i * En];
#pragma unroll
        for (int e = 0; e < En; e++) p[e] += v * w[e];
    }
#pragma unroll
    for (int o = 16; o; o >>= 1)
#pragma unroll
        for (int e = 0; e < En; e++) p[e] += __shfl_xor_sync(0xffffffffu, p[e], o);
    if (lane == 0) {
#pragma unroll
        for (int e = 0; e < En; e++) p[e] += g_bc[e];
        int i1 = 0;
        for (int e = 1; e < En; e++) if (p[e] > p[i1]) i1 = e;
        int i2 = -1;
        for (int e = 0; e < En; e++)
            if (e != i1 && (i2 < 0 || p[e] > p[i2])) i2 = e;
        float w1 = 1.f / (1.f + expf(p[i2] - p[i1]));
        g_gi[warp * 2] = i1; g_gi[warp * 2 + 1] = i2;
        g_gw[warp * 2] = w1; g_gw[warp * 2 + 1] = 1.f - w1;
        atomicAdd(&g_cnt[i1], 1);
        atomicAdd(&g_cnt[i2], 1);
    }
}

__global__ void k_off() {
    int a = 0;
    for (int e = 0; e < En; e++) { g_off[e] = a; a += g_cnt[e]; g_fill[e] = 0; }
}

__global__ void k_scatter() {
    int t = blockIdx.x * blockDim.x + threadIdx.x;
    if (t >= Tn) return;
#pragma unroll
    for (int k = 0; k < 2; k++) {
        int e = g_gi[t * 2 + k];
        int slot = g_off[e] + atomicAdd(&g_fill[e], 1);
        g_tok[slot] = t;
        g_tk[slot]  = k;
        g_tw[slot]  = g_gw[t * 2 + k];
    }
}

// ==== lin = x @ W^T + b : R9 pipelined ldmatrix GEMM (proven 91.5us) =======
__global__ void __launch_bounds__(256) k_lin(const float* __restrict__ x,
                                             const float* __restrict__ W,
                                             const float* __restrict__ bias)
{
    extern __shared__ float sm[];
    constexpr int STR = 36;
    constexpr uint32_t ASTG = 128 * STR * 4, BSTG = 128 * STR * 4;
    float* Asm = sm;                      // [2][128][36]
    float* Bsm = sm + 2 * 128 * STR;      // [2][128][36]
    int row0 = blockIdx.x * 128, col0 = blockIdx.y * 128;
    int tid = threadIdx.x, warp = tid >> 5, lane = tid & 31;
    int warpM = warp >> 1, warpN = warp & 1;
    int grp = lane >> 2, tig = lane & 3;
    int mBase = warpM * 32, nBase = warpN * 64;
    uint32_t Au = s2u(Asm), Bu = s2u(Bsm);

    int ar = tid >> 1, ac = (tid & 1) * 16;
    const float* asrc = x + (size_t)(row0 + ar) * Dn + ac;
    const float* bsrc = W + (size_t)(col0 + ar) * Dn + ac;
    uint32_t aDst0 = Au + ((uint32_t)ar * STR + ac) * 4;
    uint32_t bDst0 = Bu + ((uint32_t)ar * STR + ac) * 4;

    auto stage = [&](int it) {
        int buf = it & 1;
        const float* as = asrc + it * 32;
        const float* bs = bsrc + it * 32;
        uint32_t ad = aDst0 + buf * ASTG, bd = bDst0 + buf * BSTG;
#pragma unroll
        for (int j = 0; j < 4; j++) CPA(ad + j * 16, as + j * 4);
#pragma unroll
        for (int j = 0; j < 4; j++) CPA(bd + j * 16, bs + j * 4);
        CPCOMMIT();
    };
    stage(0);
    stage(1);

    uint32_t aB0 = Au + (uint32_t)((mBase + (lane & 7) + 8 * ((lane >> 3) & 1)) * STR
                                   + 4 * (lane >> 4)) * 4;
    uint32_t aB1 = aB0 + 16 * STR * 4;
    uint32_t bB[4];
#pragma unroll
    for (int p = 0; p < 4; p++)
        bB[p] = Bu + (uint32_t)((nBase + p * 16 + (lane & 7) + 8 * (lane >> 4)) * STR
                                + 4 * ((lane >> 3) & 1)) * 4;

    float cc[2][8][4] = {};
    constexpr int NK = Dn / 32;
    for (int it = 0; it < NK; ++it) {
        if (it < NK - 1) { CPWAIT1(); } else { CPWAIT0(); }
        __syncthreads();
        uint32_t so = (uint32_t)(it & 1) * ASTG;
#pragma unroll
        for (int ks = 0; ks < 32; ks += 8) {
            uint32_t af0[4], af1[4], bf[4][4];
            ldmx4(af0, aB0 + so + ks * 4);
            ldmx4(af1, aB1 + so + ks * 4);
#pragma unroll
            for (int p = 0; p < 4; p++) ldmx4(bf[p], bB[p] + so + ks * 4);
#pragma unroll
            for (int p = 0; p < 4; p++) {
                mma8(cc[0][2 * p],     af0, bf[p][0], bf[p][1]);
                mma8(cc[0][2 * p + 1], af0, bf[p][2], bf[p][3]);
                mma8(cc[1][2 * p],     af1, bf[p][0], bf[p][1]);
                mma8(cc[1][2 * p + 1], af1, bf[p][2], bf[p][3]);
            }
        }
        __syncthreads();
        if (it + 2 < NK) stage(it + 2);
    }
#pragma unroll
    for (int mt = 0; mt < 2; mt++)
#pragma unroll
    for (int half = 0; half < 2; half++) {
        int r = row0 + mBase + mt * 16 + grp + half * 8;
        float* o = g_lin + (size_t)r * Dn + col0;
#pragma unroll
        for (int nt = 0; nt < 8; nt++) {
            int c = nBase + nt * 8 + 2 * tig;
            float2 v;
            v.x = cc[mt][nt][half * 2 + 0] + bias[col0 + c];
            v.y = cc[mt][nt][half * 2 + 1] + bias[col0 + c + 1];
            *(float2*)(o + c) = v;
        }
    }
}

// ==== ffn: R8 pipelined GEMM verbatim (best measured), store-only epilogue ==
// MODE 1: g_h = relu(lin[g_tok] @ w1[e] + b1)   (KD=Dn, NT=Fn)
// MODE 2: g_moe[kk][tok] = gw * (g_h @ w2[e] + b2)  (KD=Fn, NT=Dn, no atomics)
template<int KD, int NT, int MODE>
__global__ void __launch_bounds__(256) pipe_ffn(const float* __restrict__ Bw,
                                                const float* __restrict__ bias)
{
    extern __shared__ float sm[];
    constexpr int ASTR = 36, BSTR = 136;
    constexpr uint32_t ASTG = 128 * ASTR * 4, BSTG = 32 * BSTR * 4;
    float* Asm = sm;                               // [2][128][36]  ([m][k])
    float* Bsm = sm + 2 * 128 * ASTR;              // [2][32][136]  ([k][n])

    int e = blockIdx.z, cnt = g_cnt[e], row0 = blockIdx.x * 128;
    if (row0 >= cnt) return;
    int off = g_off[e], col0 = blockIdx.y * 128;
    int tid = threadIdx.x, warp = tid >> 5, lane = tid & 31;
    int warpM = warp >> 1, warpN = warp & 1;
    int grp = lane >> 2, tig = lane & 3;
    int mBase = warpM * 32, nBase = warpN * 64;

    uint32_t Au = s2u(Asm), Bu = s2u(Bsm);

    int ar = tid >> 1, ac = (tid & 1) * 16;
    const float* asrc;
    if (MODE == 1) {
        int r = row0 + ar;
        int tok = (r < cnt) ? g_tok[off + r] : g_tok[off];
        asrc = g_lin + (size_t)tok * KD;
    } else {
        int s = off + row0 + ar; if (s >= 2 * Tn) s = 0;
        asrc = g_h + (size_t)s * KD;
    }
    int br = tid >> 3, bc4 = (tid & 7) * 4;
    const float* bsrc = Bw + (size_t)e * KD * NT + (size_t)br * NT + col0 + bc4;

    uint32_t aDst0 = Au + ((uint32_t)ar * ASTR + ac) * 4;
    uint32_t bDst0 = Bu + ((uint32_t)br * BSTR + bc4) * 4;

    auto stage = [&](int it) {
        int buf = it & 1;
        int k0 = it * 32;
        uint32_t ad = aDst0 + buf * ASTG;
        const float* as = asrc + k0 + ac;
#pragma unroll
        for (int j = 0; j < 4; j++) CPA(ad + j * 16, as + j * 4);
        uint32_t bd = bDst0 + buf * BSTG;
        const float* bs = bsrc + (size_t)k0 * NT;
#pragma unroll
        for (int j = 0; j < 4; j++) CPA(bd + j * 128, bs + j * 32);
        CPCOMMIT();
    };

    stage(0);
    stage(1);

    float cc[2][8][4] = {};
    constexpr int NK = KD / 32;
    for (int it = 0; it < NK; ++it) {
        if (it == NK - 1) { CPWAIT0(); } else { CPWAIT1(); }
        __syncthreads();
        int buf = it & 1;
        const float* Af = Asm + buf * 128 * ASTR;
        const float* Bf = Bsm + buf * 32 * BSTR;
#pragma unroll
        for (int ks = 0; ks < 32; ks += 8) {
            uint32_t af[2][4];
#pragma unroll
            for (int mt = 0; mt < 2; mt++) {
                int m = mBase + mt * 16 + grp;
                af[mt][0] = __float_as_uint(Af[m * ASTR + ks + tig]);
                af[mt][1] = __float_as_uint(Af[(m + 8) * ASTR + ks + tig]);
                af[mt][2] = __float_as_uint(Af[m * ASTR + ks + tig + 4]);
                af[mt][3] = __float_as_uint(Af[(m + 8) * ASTR + ks + tig + 4]);
            }
#pragma unroll
            for (int nt = 0; nt < 8; nt++) {
                int n = nBase + nt * 8 + grp;
                uint32_t b0 = __float_as_uint(Bf[(ks + tig) * BSTR + n]);
                uint32_t b1 = __float_as_uint(Bf[(ks + tig + 4) * BSTR + n]);
                mma8(cc[0][nt], af[0], b0, b1);
                mma8(cc[1][nt], af[1], b0, b1);
            }
        }
        __syncthreads();
        if (it + 2 < NK) stage(it + 2);
    }

#pragma unroll
    for (int mt = 0; mt < 2; mt++)
#pragma unroll
    for (int half = 0; half < 2; half++) {
        int r = row0 + mBase + mt * 16 + grp + half * 8;
        if (r >= cnt) continue;
        int slot = off + r;
        if (MODE == 1) {
            float* o = g_h + (size_t)slot * Fn + col0;
#pragma unroll
            for (int nt = 0; nt < 8; nt++) {
                int c = nBase + nt * 8 + 2 * tig;
                float2 v;
                v.x = fmaxf(cc[mt][nt][half * 2 + 0] + bias[e * Fn + col0 + c], 0.f);
                v.y = fmaxf(cc[mt][nt][half * 2 + 1] + bias[e * Fn + col0 + c + 1], 0.f);
                *(float2*)(o + c) = v;
            }
        } else {
            int tok = g_tok[slot];
            int kk  = g_tk[slot];
            float gw = g_tw[slot];
            float* o = g_moe + ((size_t)kk * Tn + tok) * Dn + col0;
#pragma unroll
            for (int nt = 0; nt < 8; nt++) {
                int c = nBase + nt * 8 + 2 * tig;
                float2 v;
                v.x = gw * (cc[mt][nt][half * 2 + 0] + bias[e * Dn + col0 + c]);
                v.y = gw * (cc[mt][nt][half * 2 + 1] + bias[e * Dn + col0 + c + 1]);
                *(float2*)(o + c) = v;
            }
        }
    }
}

// ---------------- mean pool (x + moe0 + moe1) + loss ----------------
__global__ void k_sent(const float* __restrict__ x, float* out) {
    int i = blockIdx.x * blockDim.x + threadIdx.x;
    if (i == 0) out[0] = 0.f;
    if (i >= Bb * Dn) return;
    int b = i >> 10, d = i & 1023;
    size_t base = (size_t)(b * Sn) * Dn + d;
    const float* px = x + base;
    const float* m0 = g_moe + base;
    const float* m1 = g_moe + (size_t)Tn * Dn + base;
    float s = 0.f;
    for (int si = 0; si < Sn; si++)
        s += px[si * Dn] + m0[si * Dn] + m1[si * Dn];
    g_sent[i] = s * (1.f / Sn);
}

__global__ void k_loss(const int* __restrict__ y, float* out) {
    int b = blockIdx.x, tid = threadIdx.x;
    __shared__ float red[256];
    const float* s = &g_sent[b * Dn];
    float m = -1e30f;
    for (int i = tid; i < Dn; i += 256) m = fmaxf(m, s[i]);
    red[tid] = m; __syncthreads();
    for (int o = 128; o; o >>= 1) {
        if (tid < o) red[tid] = fmaxf(red[tid], red[tid + o]);
        __syncthreads();
    }
    float mx = red[0]; __syncthreads();
    float sum = 0.f;
    for (int i = tid; i < Dn; i += 256) sum += expf(s[i] - mx);
    red[tid] = sum; __syncthreads();
    for (int o = 128; o; o >>= 1) {
        if (tid < o) red[tid] += red[tid + o];
        __syncthreads();
    }
    if (tid == 0)
        atomicAdd(out, -(s[y[b]] - (mx + logf(red[0]))) * (1.f / Bb));
}

// ---------------- launch ----------------
extern "C" void kernel_launch(void* const* d_in, const int* in_sizes, int n_in,
                              void* d_out, int out_size) {
    const float* x  = (const float*)d_in[0];
    const int*   y  = (const int*)d_in[1];
    const float* W  = (const float*)d_in[2];
    const float* bb = (const float*)d_in[3];
    const float* Wg = (const float*)d_in[4];
    const float* w1 = (const float*)d_in[5];
    const float* b1 = (const float*)d_in[6];
    const float* w2 = (const float*)d_in[7];
    const float* b2 = (const float*)d_in[8];
    float* out = (float*)d_out;

    constexpr int SMEM_LIN = 4 * 128 * 36 * 4;                    // 73728
    constexpr int SMEM_FFN = (2 * 128 * 36 + 2 * 32 * 136) * 4;   // 71680
    static int done = 0;
    if (!done) {
        cudaFuncSetAttribute((const void*)k_lin,
                             cudaFuncAttributeMaxDynamicSharedMemorySize, SMEM_LIN);
        cudaFuncSetAttribute((const void*)pipe_ffn<Dn, Fn, 1>,
                             cudaFuncAttributeMaxDynamicSharedMemorySize, SMEM_FFN);
        cudaFuncSetAttribute((const void*)pipe_ffn<Fn, Dn, 2>,
                             cudaFuncAttributeMaxDynamicSharedMemorySize, SMEM_FFN);
        done = 1;
    }

    k_wc<<<Dn / 256, 256>>>(W, Wg, bb);
    k_init<<<1, 32>>>();
    k_gate2<<<(Tn * 32) / 256, 256>>>(x);
    k_lin<<<dim3(Tn / 128, Dn / 128), 256, SMEM_LIN>>>(x, W, bb);
    k_off<<<1, 1>>>();
    k_scatter<<<Tn / 256, 256>>>();
    pipe_ffn<Dn, Fn, 1><<<dim3(Tn / 128, Fn / 128, En), 256, SMEM_FFN>>>(w1, b1);
    pipe_ffn<Fn, Dn, 2><<<dim3(Tn / 128, Dn / 128, En), 256, SMEM_FFN>>>(w2, b2);
    k_sent<<<(Bb * Dn + 255) / 256, 256>>>(x, out);
    k_loss<<<Bb, 256>>>(y, out);
}